// round 4
// baseline (speedup 1.0000x reference)
#include <cuda_runtime.h>
#include <cuda_bf16.h>
#include <math.h>

#define NN 50000
#define EE 400000
#define EP (EE + NN)   // edges + self loops = 450000

// ---------------- scratch (static __device__, no allocations) ----------------
__device__ float g_h1[(size_t)NN * 512];   // layer1 x@W1^T
__device__ float g_o1[(size_t)NN * 512];   // layer1 output (elu'd)
__device__ float g_h2[(size_t)NN * 128];
__device__ float g_o2[(size_t)NN * 128];
__device__ float g_h3[NN * 8];
__device__ float g_o3[NN * 8];
__device__ float g_s[NN * 4];
__device__ float g_d[NN * 4];
__device__ float g_s3[NN];
__device__ float g_d3[NN];
__device__ float g_e[(size_t)EP * 4];      // per-edge e / ex staging (4 heads)
__device__ int   g_deg[NN];
__device__ int   g_rowptr[NN + 1];
__device__ int   g_cursor[NN];
__device__ int   g_adj[EP];                // src per in-edge (CSR by dst)

__device__ __forceinline__ float lrelu(float x) { return x > 0.f ? x : 0.2f * x; }
__device__ __forceinline__ float eluf(float x)  { return x > 0.f ? x : expm1f(x); }
__device__ __forceinline__ float sel4(float a, float b, float c, float d, int h) {
    return h == 0 ? a : (h == 1 ? b : (h == 2 ? c : d));
}

// ---------------- CSR build ----------------
__global__ void k_initdeg() {
    int n = blockIdx.x * blockDim.x + threadIdx.x;
    if (n < NN) g_deg[n] = 1;   // self loop
}

__global__ void k_count(const int* __restrict__ ei) {
    int e = blockIdx.x * blockDim.x + threadIdx.x;
    if (e < EE) atomicAdd(&g_deg[ei[EE + e]], 1);
}

__global__ void k_scan() {
    __shared__ int sm[1024];
    __shared__ int carry;
    int tid = threadIdx.x;
    if (tid == 0) { carry = 0; g_rowptr[0] = 0; }
    __syncthreads();
    for (int base = 0; base < NN; base += 1024) {
        int i = base + tid;
        int v = (i < NN) ? g_deg[i] : 0;
        sm[tid] = v;
        __syncthreads();
        for (int o = 1; o < 1024; o <<= 1) {
            int t = (tid >= o) ? sm[tid - o] : 0;
            __syncthreads();
            sm[tid] += t;
            __syncthreads();
        }
        int inc = sm[tid] + carry;
        if (i < NN) g_rowptr[i + 1] = inc;
        __syncthreads();
        if (tid == 1023) carry = inc;
        __syncthreads();
    }
}

__global__ void k_prep() {
    int n = blockIdx.x * blockDim.x + threadIdx.x;
    if (n < NN) {
        int r = g_rowptr[n];
        g_adj[r] = n;            // self loop placed first
        g_cursor[n] = r + 1;
    }
}

__global__ void k_scatter(const int* __restrict__ ei) {
    int e = blockIdx.x * blockDim.x + threadIdx.x;
    if (e < EE) {
        int src = ei[e], dst = ei[EE + e];
        int p = atomicAdd(&g_cursor[dst], 1);
        g_adj[p] = src;
    }
}

// ---------------- SGEMM: C[M,N] = A[M,K] * B[N,K]^T  (NT, both K-contig) -----
// BM=BN=128, BK=8, 256 threads, 8x8 micro-tile
template<int LAYER>
__global__ void __launch_bounds__(256) gemm_k(const float* __restrict__ Aext,
                                              const float* __restrict__ B,
                                              int M, int N, int K) {
    const float* A = (LAYER == 1) ? Aext : g_o1;
    float* C = (LAYER == 1) ? g_h1 : g_h2;
    __shared__ float As[8][128];
    __shared__ float Bs[8][128];
    int tid = threadIdx.x;
    int tx = tid & 15, ty = tid >> 4;
    int bm = blockIdx.y * 128;
    int bn = blockIdx.x * 128;
    float acc[8][8];
#pragma unroll
    for (int i = 0; i < 8; i++)
#pragma unroll
        for (int j = 0; j < 8; j++) acc[i][j] = 0.f;

    int lr = tid >> 1;          // 0..127
    int lc = (tid & 1) * 4;     // 0 or 4
    const float* Aptr = A + (size_t)(bm + lr) * K + lc;
    const float* Bptr = B + (size_t)(bn + lr) * K + lc;
    bool aval = (bm + lr) < M;

    for (int k0 = 0; k0 < K; k0 += 8) {
        float4 av = aval ? *(const float4*)(Aptr + k0) : make_float4(0, 0, 0, 0);
        float4 bv = *(const float4*)(Bptr + k0);
        As[lc + 0][lr] = av.x; As[lc + 1][lr] = av.y;
        As[lc + 2][lr] = av.z; As[lc + 3][lr] = av.w;
        Bs[lc + 0][lr] = bv.x; Bs[lc + 1][lr] = bv.y;
        Bs[lc + 2][lr] = bv.z; Bs[lc + 3][lr] = bv.w;
        __syncthreads();
#pragma unroll
        for (int k = 0; k < 8; k++) {
            float4 a0 = *(const float4*)&As[k][ty * 8];
            float4 a1 = *(const float4*)&As[k][ty * 8 + 4];
            float4 b0 = *(const float4*)&Bs[k][tx * 8];
            float4 b1 = *(const float4*)&Bs[k][tx * 8 + 4];
            float ra[8] = {a0.x, a0.y, a0.z, a0.w, a1.x, a1.y, a1.z, a1.w};
            float rb[8] = {b0.x, b0.y, b0.z, b0.w, b1.x, b1.y, b1.z, b1.w};
#pragma unroll
            for (int i = 0; i < 8; i++)
#pragma unroll
                for (int j = 0; j < 8; j++) acc[i][j] += ra[i] * rb[j];
        }
        __syncthreads();
    }
#pragma unroll
    for (int i = 0; i < 8; i++) {
        int gr = bm + ty * 8 + i;
        if (gr < M) {
            float4 v0 = make_float4(acc[i][0], acc[i][1], acc[i][2], acc[i][3]);
            float4 v1 = make_float4(acc[i][4], acc[i][5], acc[i][6], acc[i][7]);
            *(float4*)(C + (size_t)gr * N + bn + tx * 8) = v0;
            *(float4*)(C + (size_t)gr * N + bn + tx * 8 + 4) = v1;
        }
    }
}

// ---------------- attention coefficients: s[n,h]=h·a_s, d[n,h]=h·a_d --------
template<int CT>
__global__ void k_sd(const float* __restrict__ as, const float* __restrict__ ad) {
    const float* __restrict__ h = (CT == 512) ? g_h1 : g_h2;
    int w = (blockIdx.x * blockDim.x + threadIdx.x) >> 5;
    int lane = threadIdx.x & 31;
    if (w >= NN) return;
    constexpr int NV = CT / 128;
    const float4* hp = (const float4*)(h + (size_t)w * CT) + lane;
    const float4* ap = (const float4*)as + lane;
    const float4* bp = (const float4*)ad + lane;
    float ps[4] = {0, 0, 0, 0}, pd[4] = {0, 0, 0, 0};
    int hsel = lane >> 3;
#pragma unroll
    for (int i = 0; i < NV; i++) {
        float4 hv = hp[32 * i], av = ap[32 * i], dv = bp[32 * i];
        float s = hv.x * av.x + hv.y * av.y + hv.z * av.z + hv.w * av.w;
        float t = hv.x * dv.x + hv.y * dv.y + hv.z * dv.z + hv.w * dv.w;
        if (CT == 512) { ps[i] += s; pd[i] += t; }
        else {
#pragma unroll
            for (int k = 0; k < 4; k++) {
                ps[k] += (hsel == k) ? s : 0.f;
                pd[k] += (hsel == k) ? t : 0.f;
            }
        }
    }
#pragma unroll
    for (int o = 16; o; o >>= 1) {
#pragma unroll
        for (int k = 0; k < 4; k++) {
            ps[k] += __shfl_xor_sync(0xffffffffu, ps[k], o);
            pd[k] += __shfl_xor_sync(0xffffffffu, pd[k], o);
        }
    }
    if (lane == 0) {
#pragma unroll
        for (int k = 0; k < 4; k++) { g_s[4 * w + k] = ps[k]; g_d[4 * w + k] = pd[k]; }
    }
}

// ---------------- warp-per-node segment softmax + aggregation ---------------
template<int CT>
__global__ void k_agg(const float* __restrict__ bias) {
    const float* __restrict__ h = (CT == 512) ? g_h1 : g_h2;
    float* __restrict__ out = (CT == 512) ? g_o1 : g_o2;
    int w = (blockIdx.x * blockDim.x + threadIdx.x) >> 5;
    int lane = threadIdx.x & 31;
    if (w >= NN) return;
    int beg = g_rowptr[w], end = g_rowptr[w + 1];
    float4 dv = *(const float4*)(g_d + 4 * w);

    // pass 1: e = lrelu(s[src]+d[dst]); stage e; per-lane max
    float m0 = -1e30f, m1 = -1e30f, m2 = -1e30f, m3 = -1e30f;
    for (int j = beg + lane; j < end; j += 32) {
        int src = g_adj[j];
        float4 sv = *(const float4*)(g_s + 4 * src);
        float e0 = lrelu(sv.x + dv.x), e1 = lrelu(sv.y + dv.y);
        float e2 = lrelu(sv.z + dv.z), e3 = lrelu(sv.w + dv.w);
        *(float4*)(g_e + 4 * (size_t)j) = make_float4(e0, e1, e2, e3);
        m0 = fmaxf(m0, e0); m1 = fmaxf(m1, e1);
        m2 = fmaxf(m2, e2); m3 = fmaxf(m3, e3);
    }
#pragma unroll
    for (int o = 16; o; o >>= 1) {
        m0 = fmaxf(m0, __shfl_xor_sync(0xffffffffu, m0, o));
        m1 = fmaxf(m1, __shfl_xor_sync(0xffffffffu, m1, o));
        m2 = fmaxf(m2, __shfl_xor_sync(0xffffffffu, m2, o));
        m3 = fmaxf(m3, __shfl_xor_sync(0xffffffffu, m3, o));
    }
    __syncwarp();

    // pass 2: ex = exp(e-m); stage ex; den
    float d0 = 0, d1 = 0, d2 = 0, d3 = 0;
    for (int j = beg + lane; j < end; j += 32) {
        float4 ev = *(float4*)(g_e + 4 * (size_t)j);
        float x0 = expf(ev.x - m0), x1 = expf(ev.y - m1);
        float x2 = expf(ev.z - m2), x3 = expf(ev.w - m3);
        *(float4*)(g_e + 4 * (size_t)j) = make_float4(x0, x1, x2, x3);
        d0 += x0; d1 += x1; d2 += x2; d3 += x3;
    }
#pragma unroll
    for (int o = 16; o; o >>= 1) {
        d0 += __shfl_xor_sync(0xffffffffu, d0, o);
        d1 += __shfl_xor_sync(0xffffffffu, d1, o);
        d2 += __shfl_xor_sync(0xffffffffu, d2, o);
        d3 += __shfl_xor_sync(0xffffffffu, d3, o);
    }
    __syncwarp();

    // pass 3: acc = sum ex * h[src]  (whole warp per edge, coalesced float4)
    constexpr int NV = CT / 128;
    float4 acc[NV];
#pragma unroll
    for (int i = 0; i < NV; i++) acc[i] = make_float4(0, 0, 0, 0);
    int hsel = lane >> 3;
    for (int j = beg; j < end; j++) {
        int src = g_adj[j];                               // broadcast
        float4 xv = *(const float4*)(g_e + 4 * (size_t)j); // broadcast
        const float4* hp = (const float4*)(h + (size_t)src * CT) + lane;
#pragma unroll
        for (int i = 0; i < NV; i++) {
            float4 hv = hp[32 * i];
            float wg = (CT == 512) ? sel4(xv.x, xv.y, xv.z, xv.w, i)
                                   : sel4(xv.x, xv.y, xv.z, xv.w, hsel);
            acc[i].x += wg * hv.x; acc[i].y += wg * hv.y;
            acc[i].z += wg * hv.z; acc[i].w += wg * hv.w;
        }
    }
    const float4* bp = (const float4*)bias + lane;
    float4* op = (float4*)(out + (size_t)w * CT) + lane;
#pragma unroll
    for (int i = 0; i < NV; i++) {
        float dd = (CT == 512) ? sel4(d0, d1, d2, d3, i) : sel4(d0, d1, d2, d3, hsel);
        float inv = 1.f / dd;
        float4 bv = bp[32 * i];
        float4 r;
        r.x = eluf(acc[i].x * inv + bv.x);
        r.y = eluf(acc[i].y * inv + bv.y);
        r.z = eluf(acc[i].z * inv + bv.z);
        r.w = eluf(acc[i].w * inv + bv.w);
        op[32 * i] = r;
    }
}

// ---------------- layer3: h3 = o2 @ W3^T (8 outs) + s3/d3, warp per node ----
__global__ void k_l3(const float* __restrict__ W3, const float* __restrict__ a3s,
                     const float* __restrict__ a3d) {
    int w = (blockIdx.x * blockDim.x + threadIdx.x) >> 5;
    int lane = threadIdx.x & 31;
    if (w >= NN) return;
    float4 xv = ((const float4*)(g_o2 + (size_t)w * 128))[lane];
    float p[8];
#pragma unroll
    for (int o = 0; o < 8; o++) {
        float4 wv = ((const float4*)(W3 + o * 128))[lane];
        p[o] = xv.x * wv.x + xv.y * wv.y + xv.z * wv.z + xv.w * wv.w;
    }
#pragma unroll
    for (int off = 16; off; off >>= 1)
#pragma unroll
        for (int o = 0; o < 8; o++) p[o] += __shfl_xor_sync(0xffffffffu, p[o], off);
    if (lane == 0) {
        float ss = 0.f, dd = 0.f;
#pragma unroll
        for (int o = 0; o < 8; o++) {
            g_h3[w * 8 + o] = p[o];
            ss += p[o] * a3s[o];
            dd += p[o] * a3d[o];
        }
        g_s3[w] = ss; g_d3[w] = dd;
    }
}

// ---------------- layer3 aggregation: thread per node -----------------------
__global__ void k_agg3(const float* __restrict__ b3) {
    int n = blockIdx.x * blockDim.x + threadIdx.x;
    if (n >= NN) return;
    int beg = g_rowptr[n], end = g_rowptr[n + 1];
    float dv = g_d3[n];
    float m = -1e30f;
    for (int j = beg; j < end; j++) {
        float e = lrelu(g_s3[g_adj[j]] + dv);
        m = fmaxf(m, e);
    }
    float den = 0.f;
    float4 a0 = make_float4(0, 0, 0, 0), a1 = make_float4(0, 0, 0, 0);
    for (int j = beg; j < end; j++) {
        int src = g_adj[j];
        float ex = expf(lrelu(g_s3[src] + dv) - m);
        den += ex;
        float4 h0 = *(const float4*)(g_h3 + (size_t)src * 8);
        float4 h1 = *(const float4*)(g_h3 + (size_t)src * 8 + 4);
        a0.x += ex * h0.x; a0.y += ex * h0.y; a0.z += ex * h0.z; a0.w += ex * h0.w;
        a1.x += ex * h1.x; a1.y += ex * h1.y; a1.z += ex * h1.z; a1.w += ex * h1.w;
    }
    float inv = 1.f / den;
    float4 r0, r1;
    r0.x = eluf(a0.x * inv + b3[0]); r0.y = eluf(a0.y * inv + b3[1]);
    r0.z = eluf(a0.z * inv + b3[2]); r0.w = eluf(a0.w * inv + b3[3]);
    r1.x = eluf(a1.x * inv + b3[4]); r1.y = eluf(a1.y * inv + b3[5]);
    r1.z = eluf(a1.z * inv + b3[6]); r1.w = eluf(a1.w * inv + b3[7]);
    *(float4*)(g_o3 + (size_t)n * 8) = r0;
    *(float4*)(g_o3 + (size_t)n * 8 + 4) = r1;
}

// ---------------- edge MLP ----------------
__global__ void k_mlp(const int* __restrict__ ei, const float* __restrict__ ea,
                      const float* __restrict__ yr, const float* __restrict__ qt,
                      const float* __restrict__ f1w, const float* __restrict__ f1b,
                      const float* __restrict__ f2w, const float* __restrict__ f2b,
                      float* __restrict__ out) {
    __shared__ float w1s[16 * 19], b1s[16], w2s[16];
    __shared__ float b2s;
    int t = threadIdx.x;
    for (int i = t; i < 16 * 19; i += blockDim.x) w1s[i] = f1w[i];
    if (t < 16) { b1s[t] = f1b[t]; w2s[t] = f2w[t]; }
    if (t == 0) b2s = f2b[0];
    __syncthreads();
    int e = blockIdx.x * blockDim.x + t;
    if (e >= EE) return;
    int src = ei[e], dst = ei[EE + e];
    float4 s0 = *(const float4*)(g_o3 + (size_t)src * 8);
    float4 s1 = *(const float4*)(g_o3 + (size_t)src * 8 + 4);
    float4 q0 = *(const float4*)(g_o3 + (size_t)dst * 8);
    float4 q1 = *(const float4*)(g_o3 + (size_t)dst * 8 + 4);
    float z16 = ea[e], z17 = yr[e], z18 = qt[e];
    float res = b2s;
#pragma unroll
    for (int o = 0; o < 16; o++) {
        const float* wr = &w1s[o * 19];
        float a = b1s[o]
            + wr[0] * s0.x + wr[1] * s0.y + wr[2] * s0.z + wr[3] * s0.w
            + wr[4] * s1.x + wr[5] * s1.y + wr[6] * s1.z + wr[7] * s1.w
            + wr[8] * q0.x + wr[9] * q0.y + wr[10] * q0.z + wr[11] * q0.w
            + wr[12] * q1.x + wr[13] * q1.y + wr[14] * q1.z + wr[15] * q1.w
            + wr[16] * z16 + wr[17] * z17 + wr[18] * z18;
        res += w2s[o] * fmaxf(a, 0.f);
    }
    out[e] = res;
}

// ---------------- host ----------------
extern "C" void kernel_launch(void* const* d_in, const int* in_sizes, int n_in,
                              void* d_out, int out_size) {
    const float* x   = (const float*)d_in[0];
    const int*   ei  = (const int*)d_in[1];
    const float* ea  = (const float*)d_in[2];
    const float* yr  = (const float*)d_in[3];
    const float* qt  = (const float*)d_in[4];
    const float* W1  = (const float*)d_in[5];
    const float* a1s = (const float*)d_in[6];
    const float* a1d = (const float*)d_in[7];
    const float* b1  = (const float*)d_in[8];
    const float* W2  = (const float*)d_in[9];
    const float* a2s = (const float*)d_in[10];
    const float* a2d = (const float*)d_in[11];
    const float* b2  = (const float*)d_in[12];
    const float* W3  = (const float*)d_in[13];
    const float* a3s = (const float*)d_in[14];
    const float* a3d = (const float*)d_in[15];
    const float* b3  = (const float*)d_in[16];
    const float* f1w = (const float*)d_in[17];
    const float* f1b = (const float*)d_in[18];
    const float* f2w = (const float*)d_in[19];
    const float* f2b = (const float*)d_in[20];
    float* out = (float*)d_out;

    // CSR build (dst-sorted adjacency, self loop first per node)
    k_initdeg<<<(NN + 255) / 256, 256>>>();
    k_count<<<(EE + 255) / 256, 256>>>(ei);
    k_scan<<<1, 1024>>>();
    k_prep<<<(NN + 255) / 256, 256>>>();
    k_scatter<<<(EE + 255) / 256, 256>>>(ei);

    int wblocks = (NN * 32 + 255) / 256;   // warp-per-node launches

    // layer 1: 128 -> 4x128
    dim3 g1(512 / 128, (NN + 127) / 128);
    gemm_k<1><<<g1, 256>>>(x, W1, NN, 512, 128);
    k_sd<512><<<wblocks, 256>>>(a1s, a1d);
    k_agg<512><<<wblocks, 256>>>(b1);

    // layer 2: 512 -> 4x32
    dim3 g2(128 / 128, (NN + 127) / 128);
    gemm_k<2><<<g2, 256>>>(nullptr, W2, NN, 128, 512);
    k_sd<128><<<wblocks, 256>>>(a2s, a2d);
    k_agg<128><<<wblocks, 256>>>(b2);

    // layer 3: 128 -> 1x8 (gemm + s/d fused), then aggregation
    k_l3<<<wblocks, 256>>>(W3, a3s, a3d);
    k_agg3<<<(NN + 255) / 256, 256>>>(b3);

    // edge MLP
    k_mlp<<<(EE + 255) / 256, 256>>>(ei, ea, yr, qt, f1w, f1b, f2w, f2b, out);
}

// round 8
// speedup vs baseline: 1.6399x; 1.6399x over previous
#include <cuda_runtime.h>
#include <cuda_bf16.h>
#include <math.h>

#define NN 50000
#define EE 400000
#define EP (EE + NN)   // edges + self loops = 450000

// ---------------- scratch (static __device__, no allocations) ----------------
__device__ float g_h1[(size_t)NN * 512];   // layer1 x@W1^T
__device__ float g_o1[(size_t)NN * 512];   // layer1 output (elu'd)
__device__ float g_h2[(size_t)NN * 128];
__device__ float g_o2[(size_t)NN * 128];
__device__ float g_h3[NN * 8];
__device__ float g_o3[NN * 8];
__device__ float g_s[NN * 4];
__device__ float g_d[NN * 4];
__device__ float g_s3[NN];
__device__ float g_d3[NN];
__device__ float g_e[(size_t)EP * 4];      // per-edge e / ex staging (4 heads)
__device__ int   g_deg[NN];
__device__ int   g_rowptr[NN + 1];
__device__ int   g_cursor[NN];
__device__ int   g_adj[EP];                // src per in-edge (CSR by dst)

__device__ __forceinline__ float lrelu(float x) { return x > 0.f ? x : 0.2f * x; }
__device__ __forceinline__ float eluf(float x)  { return x > 0.f ? x : expm1f(x); }
__device__ __forceinline__ float sel4(float a, float b, float c, float d, int h) {
    return h == 0 ? a : (h == 1 ? b : (h == 2 ? c : d));
}
__device__ __forceinline__ unsigned t32(float f) {
    unsigned u;
    asm("cvt.rna.tf32.f32 %0, %1;" : "=r"(u) : "f"(f));
    return u;
}
__device__ __forceinline__ void mma8(float* c, const unsigned* a, const unsigned* b) {
    asm volatile(
        "mma.sync.aligned.m16n8k8.row.col.f32.tf32.tf32.f32 "
        "{%0,%1,%2,%3}, {%4,%5,%6,%7}, {%8,%9}, {%0,%1,%2,%3};"
        : "+f"(c[0]), "+f"(c[1]), "+f"(c[2]), "+f"(c[3])
        : "r"(a[0]), "r"(a[1]), "r"(a[2]), "r"(a[3]), "r"(b[0]), "r"(b[1]));
}

// ---------------- CSR build ----------------
__global__ void k_initdeg() {
    int n = blockIdx.x * blockDim.x + threadIdx.x;
    if (n < NN) g_deg[n] = 1;   // self loop
}

__global__ void k_count(const int* __restrict__ ei) {
    int e = blockIdx.x * blockDim.x + threadIdx.x;
    if (e < EE) atomicAdd(&g_deg[ei[EE + e]], 1);
}

__global__ void k_scan() {
    __shared__ int warpsum[32];
    __shared__ int carry_s;
    int tid = threadIdx.x;
    int lane = tid & 31, wid = tid >> 5;
    if (tid == 0) { carry_s = 0; g_rowptr[0] = 0; }
    __syncthreads();
    for (int base = 0; base < NN; base += 1024) {
        int i = base + tid;
        int v = (i < NN) ? g_deg[i] : 0;
        int s = v;
#pragma unroll
        for (int o = 1; o < 32; o <<= 1) {
            int t = __shfl_up_sync(0xffffffffu, s, o);
            if (lane >= o) s += t;
        }
        if (lane == 31) warpsum[wid] = s;
        __syncthreads();
        if (wid == 0) {
            int ws = warpsum[lane];
#pragma unroll
            for (int o = 1; o < 32; o <<= 1) {
                int t = __shfl_up_sync(0xffffffffu, ws, o);
                if (lane >= o) ws += t;
            }
            warpsum[lane] = ws;
        }
        __syncthreads();
        int inc = s + (wid ? warpsum[wid - 1] : 0) + carry_s;
        if (i < NN) g_rowptr[i + 1] = inc;
        __syncthreads();
        if (tid == 1023) carry_s = inc;
        __syncthreads();
    }
}

__global__ void k_prep() {
    int n = blockIdx.x * blockDim.x + threadIdx.x;
    if (n < NN) {
        int r = g_rowptr[n];
        g_adj[r] = n;            // self loop placed first
        g_cursor[n] = r + 1;
    }
}

__global__ void k_scatter(const int* __restrict__ ei) {
    int e = blockIdx.x * blockDim.x + threadIdx.x;
    if (e < EE) {
        int src = ei[e], dst = ei[EE + e];
        int p = atomicAdd(&g_cursor[dst], 1);
        g_adj[p] = src;
    }
}

// ---------------- TF32 tensor-core GEMM: C[M,N] = A[M,K] * B[N,K]^T ---------
// Block tile 128x64, 8 warps (4m x 2n), warp tile 32x32, BK=32.
// smem stride 36 floats -> conflict-free fragment reads.
template<int LAYER>
__global__ void __launch_bounds__(256) gemm_tc(const float* __restrict__ Aext,
                                               const float* __restrict__ B,
                                               int M, int N, int K) {
    const float* A = (LAYER == 1) ? Aext : g_o1;
    float* C = (LAYER == 1) ? g_h1 : g_h2;
    __shared__ unsigned As[128][36];
    __shared__ unsigned Bs[64][36];
    int tid = threadIdx.x;
    int lane = tid & 31, warp = tid >> 5;
    int wm = (warp & 3) * 32;
    int wn = (warp >> 2) * 32;
    int gid = lane >> 2, tig = lane & 3;
    int bm = blockIdx.y * 128, bn = blockIdx.x * 64;

    float acc[2][4][4];
#pragma unroll
    for (int mf = 0; mf < 2; mf++)
#pragma unroll
        for (int nf = 0; nf < 4; nf++)
#pragma unroll
            for (int k = 0; k < 4; k++) acc[mf][nf][k] = 0.f;

    int lr = tid >> 3;          // 0..31
    int lc = (tid & 7) * 4;     // 0,4,...,28
    int nk = K / 32;

    float4 pa[4], pb[2];
    // load first K-slab
#pragma unroll
    for (int i = 0; i < 4; i++) {
        int row = bm + lr + 32 * i;
        pa[i] = (row < M) ? *(const float4*)(A + (size_t)row * K + lc)
                          : make_float4(0, 0, 0, 0);
    }
#pragma unroll
    for (int i = 0; i < 2; i++) {
        int row = bn + lr + 32 * i;
        pb[i] = *(const float4*)(B + (size_t)row * K + lc);
    }
#pragma unroll
    for (int i = 0; i < 4; i++) {
        As[lr + 32 * i][lc + 0] = t32(pa[i].x);
        As[lr + 32 * i][lc + 1] = t32(pa[i].y);
        As[lr + 32 * i][lc + 2] = t32(pa[i].z);
        As[lr + 32 * i][lc + 3] = t32(pa[i].w);
    }
#pragma unroll
    for (int i = 0; i < 2; i++) {
        Bs[lr + 32 * i][lc + 0] = t32(pb[i].x);
        Bs[lr + 32 * i][lc + 1] = t32(pb[i].y);
        Bs[lr + 32 * i][lc + 2] = t32(pb[i].z);
        Bs[lr + 32 * i][lc + 3] = t32(pb[i].w);
    }
    __syncthreads();

    for (int it = 0; it < nk; it++) {
        // prefetch next slab into registers
        if (it + 1 < nk) {
            int koff = (it + 1) * 32;
#pragma unroll
            for (int i = 0; i < 4; i++) {
                int row = bm + lr + 32 * i;
                pa[i] = (row < M) ? *(const float4*)(A + (size_t)row * K + koff + lc)
                                  : make_float4(0, 0, 0, 0);
            }
#pragma unroll
            for (int i = 0; i < 2; i++) {
                int row = bn + lr + 32 * i;
                pb[i] = *(const float4*)(B + (size_t)row * K + koff + lc);
            }
        }
        // compute 4 k-steps of 8
#pragma unroll
        for (int ks = 0; ks < 4; ks++) {
            int kk = ks * 8;
            unsigned a[2][4], b[4][2];
#pragma unroll
            for (int mf = 0; mf < 2; mf++) {
                int r = wm + mf * 16 + gid;
                a[mf][0] = As[r][kk + tig];
                a[mf][1] = As[r + 8][kk + tig];
                a[mf][2] = As[r][kk + tig + 4];
                a[mf][3] = As[r + 8][kk + tig + 4];
            }
#pragma unroll
            for (int nf = 0; nf < 4; nf++) {
                int r = wn + nf * 8 + gid;
                b[nf][0] = Bs[r][kk + tig];
                b[nf][1] = Bs[r][kk + tig + 4];
            }
#pragma unroll
            for (int mf = 0; mf < 2; mf++)
#pragma unroll
                for (int nf = 0; nf < 4; nf++) mma8(acc[mf][nf], a[mf], b[nf]);
        }
        __syncthreads();
        if (it + 1 < nk) {
#pragma unroll
            for (int i = 0; i < 4; i++) {
                As[lr + 32 * i][lc + 0] = t32(pa[i].x);
                As[lr + 32 * i][lc + 1] = t32(pa[i].y);
                As[lr + 32 * i][lc + 2] = t32(pa[i].z);
                As[lr + 32 * i][lc + 3] = t32(pa[i].w);
            }
#pragma unroll
            for (int i = 0; i < 2; i++) {
                Bs[lr + 32 * i][lc + 0] = t32(pb[i].x);
                Bs[lr + 32 * i][lc + 1] = t32(pb[i].y);
                Bs[lr + 32 * i][lc + 2] = t32(pb[i].z);
                Bs[lr + 32 * i][lc + 3] = t32(pb[i].w);
            }
            __syncthreads();
        }
    }

    // epilogue: c0/c1 at (gid, 2tig/2tig+1), c2/c3 at (gid+8, ...)
#pragma unroll
    for (int mf = 0; mf < 2; mf++)
#pragma unroll
        for (int nf = 0; nf < 4; nf++) {
            int r0 = bm + wm + mf * 16 + gid;
            int c0 = bn + wn + nf * 8 + 2 * tig;
            if (r0 < M)
                *(float2*)(C + (size_t)r0 * N + c0) =
                    make_float2(acc[mf][nf][0], acc[mf][nf][1]);
            if (r0 + 8 < M)
                *(float2*)(C + (size_t)(r0 + 8) * N + c0) =
                    make_float2(acc[mf][nf][2], acc[mf][nf][3]);
        }
}

// ---------------- attention coefficients: s[n,h]=h·a_s, d[n,h]=h·a_d --------
template<int CT>
__global__ void k_sd(const float* __restrict__ as, const float* __restrict__ ad) {
    const float* __restrict__ h = (CT == 512) ? g_h1 : g_h2;
    int w = (blockIdx.x * blockDim.x + threadIdx.x) >> 5;
    int lane = threadIdx.x & 31;
    if (w >= NN) return;
    constexpr int NV = CT / 128;
    const float4* hp = (const float4*)(h + (size_t)w * CT) + lane;
    const float4* ap = (const float4*)as + lane;
    const float4* bp = (const float4*)ad + lane;
    float ps[4] = {0, 0, 0, 0}, pd[4] = {0, 0, 0, 0};
    int hsel = lane >> 3;
#pragma unroll
    for (int i = 0; i < NV; i++) {
        float4 hv = hp[32 * i], av = ap[32 * i], dv = bp[32 * i];
        float s = hv.x * av.x + hv.y * av.y + hv.z * av.z + hv.w * av.w;
        float t = hv.x * dv.x + hv.y * dv.y + hv.z * dv.z + hv.w * dv.w;
        if (CT == 512) { ps[i] += s; pd[i] += t; }
        else {
#pragma unroll
            for (int k = 0; k < 4; k++) {
                ps[k] += (hsel == k) ? s : 0.f;
                pd[k] += (hsel == k) ? t : 0.f;
            }
        }
    }
#pragma unroll
    for (int o = 16; o; o >>= 1) {
#pragma unroll
        for (int k = 0; k < 4; k++) {
            ps[k] += __shfl_xor_sync(0xffffffffu, ps[k], o);
            pd[k] += __shfl_xor_sync(0xffffffffu, pd[k], o);
        }
    }
    if (lane == 0) {
#pragma unroll
        for (int k = 0; k < 4; k++) { g_s[4 * w + k] = ps[k]; g_d[4 * w + k] = pd[k]; }
    }
}

// ---------------- warp-per-node segment softmax + aggregation ---------------
template<int CT>
__global__ void k_agg(const float* __restrict__ bias) {
    const float* __restrict__ h = (CT == 512) ? g_h1 : g_h2;
    float* __restrict__ out = (CT == 512) ? g_o1 : g_o2;
    int w = (blockIdx.x * blockDim.x + threadIdx.x) >> 5;
    int lane = threadIdx.x & 31;
    if (w >= NN) return;
    int beg = g_rowptr[w], end = g_rowptr[w + 1];
    float4 dv = *(const float4*)(g_d + 4 * w);

    // pass 1: e = lrelu(s[src]+d[dst]); stage e; per-lane max
    float m0 = -1e30f, m1 = -1e30f, m2 = -1e30f, m3 = -1e30f;
    for (int j = beg + lane; j < end; j += 32) {
        int src = g_adj[j];
        float4 sv = *(const float4*)(g_s + 4 * src);
        float e0 = lrelu(sv.x + dv.x), e1 = lrelu(sv.y + dv.y);
        float e2 = lrelu(sv.z + dv.z), e3 = lrelu(sv.w + dv.w);
        *(float4*)(g_e + 4 * (size_t)j) = make_float4(e0, e1, e2, e3);
        m0 = fmaxf(m0, e0); m1 = fmaxf(m1, e1);
        m2 = fmaxf(m2, e2); m3 = fmaxf(m3, e3);
    }
#pragma unroll
    for (int o = 16; o; o >>= 1) {
        m0 = fmaxf(m0, __shfl_xor_sync(0xffffffffu, m0, o));
        m1 = fmaxf(m1, __shfl_xor_sync(0xffffffffu, m1, o));
        m2 = fmaxf(m2, __shfl_xor_sync(0xffffffffu, m2, o));
        m3 = fmaxf(m3, __shfl_xor_sync(0xffffffffu, m3, o));
    }
    __syncwarp();

    // pass 2: ex = exp(e-m); stage ex; den
    float d0 = 0, d1 = 0, d2 = 0, d3 = 0;
    for (int j = beg + lane; j < end; j += 32) {
        float4 ev = *(float4*)(g_e + 4 * (size_t)j);
        float x0 = expf(ev.x - m0), x1 = expf(ev.y - m1);
        float x2 = expf(ev.z - m2), x3 = expf(ev.w - m3);
        *(float4*)(g_e + 4 * (size_t)j) = make_float4(x0, x1, x2, x3);
        d0 += x0; d1 += x1; d2 += x2; d3 += x3;
    }
#pragma unroll
    for (int o = 16; o; o >>= 1) {
        d0 += __shfl_xor_sync(0xffffffffu, d0, o);
        d1 += __shfl_xor_sync(0xffffffffu, d1, o);
        d2 += __shfl_xor_sync(0xffffffffu, d2, o);
        d3 += __shfl_xor_sync(0xffffffffu, d3, o);
    }
    __syncwarp();

    // pass 3: acc = sum ex * h[src]  (whole warp per edge, coalesced float4)
    constexpr int NV = CT / 128;
    float4 acc[NV];
#pragma unroll
    for (int i = 0; i < NV; i++) acc[i] = make_float4(0, 0, 0, 0);
    int hsel = lane >> 3;
    for (int j = beg; j < end; j++) {
        int src = g_adj[j];                               // broadcast
        float4 xv = *(const float4*)(g_e + 4 * (size_t)j); // broadcast
        const float4* hp = (const float4*)(h + (size_t)src * CT) + lane;
#pragma unroll
        for (int i = 0; i < NV; i++) {
            float4 hv = hp[32 * i];
            float wg = (CT == 512) ? sel4(xv.x, xv.y, xv.z, xv.w, i)
                                   : sel4(xv.x, xv.y, xv.z, xv.w, hsel);
            acc[i].x += wg * hv.x; acc[i].y += wg * hv.y;
            acc[i].z += wg * hv.z; acc[i].w += wg * hv.w;
        }
    }
    const float4* bp = (const float4*)bias + lane;
    float4* op = (float4*)(out + (size_t)w * CT) + lane;
#pragma unroll
    for (int i = 0; i < NV; i++) {
        float dd = (CT == 512) ? sel4(d0, d1, d2, d3, i) : sel4(d0, d1, d2, d3, hsel);
        float inv = 1.f / dd;
        float4 bv = bp[32 * i];
        float4 r;
        r.x = eluf(acc[i].x * inv + bv.x);
        r.y = eluf(acc[i].y * inv + bv.y);
        r.z = eluf(acc[i].z * inv + bv.z);
        r.w = eluf(acc[i].w * inv + bv.w);
        op[32 * i] = r;
    }
}

// ---------------- layer3: h3 = o2 @ W3^T (8 outs) + s3/d3, warp per node ----
__global__ void k_l3(const float* __restrict__ W3, const float* __restrict__ a3s,
                     const float* __restrict__ a3d) {
    int w = (blockIdx.x * blockDim.x + threadIdx.x) >> 5;
    int lane = threadIdx.x & 31;
    if (w >= NN) return;
    float4 xv = ((const float4*)(g_o2 + (size_t)w * 128))[lane];
    float p[8];
#pragma unroll
    for (int o = 0; o < 8; o++) {
        float4 wv = ((const float4*)(W3 + o * 128))[lane];
        p[o] = xv.x * wv.x + xv.y * wv.y + xv.z * wv.z + xv.w * wv.w;
    }
#pragma unroll
    for (int off = 16; off; off >>= 1)
#pragma unroll
        for (int o = 0; o < 8; o++) p[o] += __shfl_xor_sync(0xffffffffu, p[o], off);
    if (lane == 0) {
        float ss = 0.f, dd = 0.f;
#pragma unroll
        for (int o = 0; o < 8; o++) {
            g_h3[w * 8 + o] = p[o];
            ss += p[o] * a3s[o];
            dd += p[o] * a3d[o];
        }
        g_s3[w] = ss; g_d3[w] = dd;
    }
}

// ---------------- layer3 aggregation: thread per node -----------------------
__global__ void k_agg3(const float* __restrict__ b3) {
    int n = blockIdx.x * blockDim.x + threadIdx.x;
    if (n >= NN) return;
    int beg = g_rowptr[n], end = g_rowptr[n + 1];
    float dv = g_d3[n];
    float m = -1e30f;
    for (int j = beg; j < end; j++) {
        float e = lrelu(g_s3[g_adj[j]] + dv);
        m = fmaxf(m, e);
    }
    float den = 0.f;
    float4 a0 = make_float4(0, 0, 0, 0), a1 = make_float4(0, 0, 0, 0);
    for (int j = beg; j < end; j++) {
        int src = g_adj[j];
        float ex = expf(lrelu(g_s3[src] + dv) - m);
        den += ex;
        float4 h0 = *(const float4*)(g_h3 + (size_t)src * 8);
        float4 h1 = *(const float4*)(g_h3 + (size_t)src * 8 + 4);
        a0.x += ex * h0.x; a0.y += ex * h0.y; a0.z += ex * h0.z; a0.w += ex * h0.w;
        a1.x += ex * h1.x; a1.y += ex * h1.y; a1.z += ex * h1.z; a1.w += ex * h1.w;
    }
    float inv = 1.f / den;
    float4 r0, r1;
    r0.x = eluf(a0.x * inv + b3[0]); r0.y = eluf(a0.y * inv + b3[1]);
    r0.z = eluf(a0.z * inv + b3[2]); r0.w = eluf(a0.w * inv + b3[3]);
    r1.x = eluf(a1.x * inv + b3[4]); r1.y = eluf(a1.y * inv + b3[5]);
    r1.z = eluf(a1.z * inv + b3[6]); r1.w = eluf(a1.w * inv + b3[7]);
    *(float4*)(g_o3 + (size_t)n * 8) = r0;
    *(float4*)(g_o3 + (size_t)n * 8 + 4) = r1;
}

// ---------------- edge MLP ----------------
__global__ void k_mlp(const int* __restrict__ ei, const float* __restrict__ ea,
                      const float* __restrict__ yr, const float* __restrict__ qt,
                      const float* __restrict__ f1w, const float* __restrict__ f1b,
                      const float* __restrict__ f2w, const float* __restrict__ f2b,
                      float* __restrict__ out) {
    __shared__ float w1s[16 * 19], b1s[16], w2s[16];
    __shared__ float b2s;
    int t = threadIdx.x;
    for (int i = t; i < 16 * 19; i += blockDim.x) w1s[i] = f1w[i];
    if (t < 16) { b1s[t] = f1b[t]; w2s[t] = f2w[t]; }
    if (t == 0) b2s = f2b[0];
    __syncthreads();
    int e = blockIdx.x * blockDim.x + t;
    if (e >= EE) return;
    int src = ei[e], dst = ei[EE + e];
    float4 s0 = *(const float4*)(g_o3 + (size_t)src * 8);
    float4 s1 = *(const float4*)(g_o3 + (size_t)src * 8 + 4);
    float4 q0 = *(const float4*)(g_o3 + (size_t)dst * 8);
    float4 q1 = *(const float4*)(g_o3 + (size_t)dst * 8 + 4);
    float z16 = ea[e], z17 = yr[e], z18 = qt[e];
    float res = b2s;
#pragma unroll
    for (int o = 0; o < 16; o++) {
        const float* wr = &w1s[o * 19];
        float a = b1s[o]
            + wr[0] * s0.x + wr[1] * s0.y + wr[2] * s0.z + wr[3] * s0.w
            + wr[4] * s1.x + wr[5] * s1.y + wr[6] * s1.z + wr[7] * s1.w
            + wr[8] * q0.x + wr[9] * q0.y + wr[10] * q0.z + wr[11] * q0.w
            + wr[12] * q1.x + wr[13] * q1.y + wr[14] * q1.z + wr[15] * q1.w
            + wr[16] * z16 + wr[17] * z17 + wr[18] * z18;
        res += w2s[o] * fmaxf(a, 0.f);
    }
    out[e] = res;
}

// ---------------- host ----------------
extern "C" void kernel_launch(void* const* d_in, const int* in_sizes, int n_in,
                              void* d_out, int out_size) {
    const float* x   = (const float*)d_in[0];
    const int*   ei  = (const int*)d_in[1];
    const float* ea  = (const float*)d_in[2];
    const float* yr  = (const float*)d_in[3];
    const float* qt  = (const float*)d_in[4];
    const float* W1  = (const float*)d_in[5];
    const float* a1s = (const float*)d_in[6];
    const float* a1d = (const float*)d_in[7];
    const float* b1  = (const float*)d_in[8];
    const float* W2  = (const float*)d_in[9];
    const float* a2s = (const float*)d_in[10];
    const float* a2d = (const float*)d_in[11];
    const float* b2  = (const float*)d_in[12];
    const float* W3  = (const float*)d_in[13];
    const float* a3s = (const float*)d_in[14];
    const float* a3d = (const float*)d_in[15];
    const float* b3  = (const float*)d_in[16];
    const float* f1w = (const float*)d_in[17];
    const float* f1b = (const float*)d_in[18];
    const float* f2w = (const float*)d_in[19];
    const float* f2b = (const float*)d_in[20];
    float* out = (float*)d_out;

    // CSR build (dst-sorted adjacency, self loop first per node)
    k_initdeg<<<(NN + 255) / 256, 256>>>();
    k_count<<<(EE + 255) / 256, 256>>>(ei);
    k_scan<<<1, 1024>>>();
    k_prep<<<(NN + 255) / 256, 256>>>();
    k_scatter<<<(EE + 255) / 256, 256>>>(ei);

    int wblocks = (NN * 32 + 255) / 256;   // warp-per-node launches

    // layer 1: 128 -> 4x128 (tf32 tensor cores)
    dim3 g1(512 / 64, (NN + 127) / 128);
    gemm_tc<1><<<g1, 256>>>(x, W1, NN, 512, 128);
    k_sd<512><<<wblocks, 256>>>(a1s, a1d);
    k_agg<512><<<wblocks, 256>>>(b1);

    // layer 2: 512 -> 4x32 (tf32 tensor cores)
    dim3 g2(128 / 64, (NN + 127) / 128);
    gemm_tc<2><<<g2, 256>>>(nullptr, W2, NN, 128, 512);
    k_sd<128><<<wblocks, 256>>>(a2s, a2d);
    k_agg<128><<<wblocks, 256>>>(b2);

    // layer 3: 128 -> 1x8 (gemm + s/d fused), then aggregation
    k_l3<<<wblocks, 256>>>(W3, a3s, a3d);
    k_agg3<<<(NN + 255) / 256, 256>>>(b3);

    // edge MLP
    k_mlp<<<(EE + 255) / 256, 256>>>(ei, ea, yr, qt, f1w, f1b, f2w, f2b, out);
}

// round 13
// speedup vs baseline: 1.8341x; 1.1184x over previous
#include <cuda_runtime.h>
#include <cuda_bf16.h>
#include <math.h>

#define NN 50000
#define EE 400000
#define EP (EE + NN)   // edges + self loops = 450000

// ---------------- scratch (static __device__, no allocations) ----------------
__device__ __nv_bfloat162 g_h1b[(size_t)NN * 256]; // layer1 x@W1^T (bf16, 512/node)
__device__ float g_o1[(size_t)NN * 512];           // layer1 output (elu'd, fp32)
__device__ __nv_bfloat162 g_h2b[(size_t)NN * 64];  // layer2 (bf16, 128/node)
__device__ float g_o2[(size_t)NN * 128];
__device__ float g_h3[NN * 8];
__device__ float g_o3[NN * 8];
__device__ float g_s[NN * 4];
__device__ float g_d[NN * 4];
__device__ float g_s3[NN];
__device__ float g_d3[NN];
__device__ float g_e[(size_t)EP * 4];      // per-edge e / ex staging (4 heads)
__device__ int   g_deg[NN];
__device__ int   g_rowptr[NN + 1];
__device__ int   g_cursor[NN];
__device__ int   g_adj[EP];                // src per in-edge (CSR by dst)
__device__ int   g_bsum[256];
__device__ int   g_boff[256];

__device__ __forceinline__ float lrelu(float x) { return x > 0.f ? x : 0.2f * x; }
__device__ __forceinline__ float eluf(float x)  { return x > 0.f ? x : expm1f(x); }
__device__ __forceinline__ float sel4(float a, float b, float c, float d, int h) {
    return h == 0 ? a : (h == 1 ? b : (h == 2 ? c : d));
}
__device__ __forceinline__ unsigned t32(float f) {
    unsigned u;
    asm("cvt.rna.tf32.f32 %0, %1;" : "=r"(u) : "f"(f));
    return u;
}
__device__ __forceinline__ void mma8(float* c, const unsigned* a, const unsigned* b) {
    asm volatile(
        "mma.sync.aligned.m16n8k8.row.col.f32.tf32.tf32.f32 "
        "{%0,%1,%2,%3}, {%4,%5,%6,%7}, {%8,%9}, {%0,%1,%2,%3};"
        : "+f"(c[0]), "+f"(c[1]), "+f"(c[2]), "+f"(c[3])
        : "r"(a[0]), "r"(a[1]), "r"(a[2]), "r"(a[3]), "r"(b[0]), "r"(b[1]));
}

// ---------------- CSR build ----------------
__global__ void k_initdeg() {
    int n = blockIdx.x * blockDim.x + threadIdx.x;
    if (n < NN) g_deg[n] = 1;   // self loop
}

__global__ void k_count(const int* __restrict__ ei) {
    int e = blockIdx.x * blockDim.x + threadIdx.x;
    if (e < EE) atomicAdd(&g_deg[ei[EE + e]], 1);
}

// block-local inclusive scan; writes local inclusive to rowptr[i+1], total to bsum
__global__ void k_scan1() {
    __shared__ int ws[8];
    int t = threadIdx.x;
    int lane = t & 31, w = t >> 5;
    int i = blockIdx.x * 256 + t;
    int v = (i < NN) ? g_deg[i] : 0;
    int s = v;
#pragma unroll
    for (int o = 1; o < 32; o <<= 1) {
        int u = __shfl_up_sync(0xffffffffu, s, o);
        if (lane >= o) s += u;
    }
    if (lane == 31) ws[w] = s;
    __syncthreads();
    if (w == 0 && lane < 8) {
        int x = ws[lane];
#pragma unroll
        for (int o = 1; o < 8; o <<= 1) {
            int u = __shfl_up_sync(0xffu, x, o);
            if (lane >= o) x += u;
        }
        ws[lane] = x;
    }
    __syncthreads();
    int incl = s + (w ? ws[w - 1] : 0);
    if (i < NN) g_rowptr[i + 1] = incl;
    if (t == 255) g_bsum[blockIdx.x] = incl;
}

// scan of 196 block sums -> exclusive offsets
__global__ void k_scan2() {
    __shared__ int ws[8];
    int t = threadIdx.x;
    int lane = t & 31, w = t >> 5;
    int v = (t < 196) ? g_bsum[t] : 0;
    int s = v;
#pragma unroll
    for (int o = 1; o < 32; o <<= 1) {
        int u = __shfl_up_sync(0xffffffffu, s, o);
        if (lane >= o) s += u;
    }
    if (lane == 31) ws[w] = s;
    __syncthreads();
    if (w == 0 && lane < 8) {
        int x = ws[lane];
#pragma unroll
        for (int o = 1; o < 8; o <<= 1) {
            int u = __shfl_up_sync(0xffu, x, o);
            if (lane >= o) x += u;
        }
        ws[lane] = x;
    }
    __syncthreads();
    int incl = s + (w ? ws[w - 1] : 0);
    if (t < 196) g_boff[t] = incl - v;   // exclusive
}

// add offsets + fused prep (self loop first, cursor init)
__global__ void k_scan3() {
    int i = blockIdx.x * 256 + threadIdx.x;
    if (i >= NN) return;
    int off = g_boff[blockIdx.x];
    int incl = g_rowptr[i + 1] + off;
    g_rowptr[i + 1] = incl;
    if (i == 0) g_rowptr[0] = 0;
    int r = incl - g_deg[i];
    g_adj[r] = i;            // self loop placed first
    g_cursor[i] = r + 1;
}

__global__ void k_scatter(const int* __restrict__ ei) {
    int e = blockIdx.x * blockDim.x + threadIdx.x;
    if (e < EE) {
        int src = ei[e], dst = ei[EE + e];
        int p = atomicAdd(&g_cursor[dst], 1);
        g_adj[p] = src;
    }
}

// ---------------- TF32 tensor-core GEMM: H[M,N] = A[M,K] * B[N,K]^T (bf16 out)
// Block tile 128x64, 8 warps (4m x 2n), warp tile 32x32, BK=32.
template<int LAYER>
__global__ void __launch_bounds__(256) gemm_tc(const float* __restrict__ Aext,
                                               const float* __restrict__ B,
                                               int M, int N, int K) {
    const float* A = (LAYER == 1) ? Aext : g_o1;
    __nv_bfloat162* H = (LAYER == 1) ? g_h1b : g_h2b;
    __shared__ unsigned As[128][36];
    __shared__ unsigned Bs[64][36];
    int tid = threadIdx.x;
    int lane = tid & 31, warp = tid >> 5;
    int wm = (warp & 3) * 32;
    int wn = (warp >> 2) * 32;
    int gid = lane >> 2, tig = lane & 3;
    int bm = blockIdx.y * 128, bn = blockIdx.x * 64;

    float acc[2][4][4];
#pragma unroll
    for (int mf = 0; mf < 2; mf++)
#pragma unroll
        for (int nf = 0; nf < 4; nf++)
#pragma unroll
            for (int k = 0; k < 4; k++) acc[mf][nf][k] = 0.f;

    int lr = tid >> 3;          // 0..31
    int lc = (tid & 7) * 4;     // 0,4,...,28
    int nk = K / 32;

    float4 pa[4], pb[2];
#pragma unroll
    for (int i = 0; i < 4; i++) {
        int row = bm + lr + 32 * i;
        pa[i] = (row < M) ? *(const float4*)(A + (size_t)row * K + lc)
                          : make_float4(0, 0, 0, 0);
    }
#pragma unroll
    for (int i = 0; i < 2; i++) {
        int row = bn + lr + 32 * i;
        pb[i] = *(const float4*)(B + (size_t)row * K + lc);
    }
#pragma unroll
    for (int i = 0; i < 4; i++) {
        As[lr + 32 * i][lc + 0] = t32(pa[i].x);
        As[lr + 32 * i][lc + 1] = t32(pa[i].y);
        As[lr + 32 * i][lc + 2] = t32(pa[i].z);
        As[lr + 32 * i][lc + 3] = t32(pa[i].w);
    }
#pragma unroll
    for (int i = 0; i < 2; i++) {
        Bs[lr + 32 * i][lc + 0] = t32(pb[i].x);
        Bs[lr + 32 * i][lc + 1] = t32(pb[i].y);
        Bs[lr + 32 * i][lc + 2] = t32(pb[i].z);
        Bs[lr + 32 * i][lc + 3] = t32(pb[i].w);
    }
    __syncthreads();

    for (int it = 0; it < nk; it++) {
        if (it + 1 < nk) {
            int koff = (it + 1) * 32;
#pragma unroll
            for (int i = 0; i < 4; i++) {
                int row = bm + lr + 32 * i;
                pa[i] = (row < M) ? *(const float4*)(A + (size_t)row * K + koff + lc)
                                  : make_float4(0, 0, 0, 0);
            }
#pragma unroll
            for (int i = 0; i < 2; i++) {
                int row = bn + lr + 32 * i;
                pb[i] = *(const float4*)(B + (size_t)row * K + koff + lc);
            }
        }
#pragma unroll
        for (int ks = 0; ks < 4; ks++) {
            int kk = ks * 8;
            unsigned a[2][4], b[4][2];
#pragma unroll
            for (int mf = 0; mf < 2; mf++) {
                int r = wm + mf * 16 + gid;
                a[mf][0] = As[r][kk + tig];
                a[mf][1] = As[r + 8][kk + tig];
                a[mf][2] = As[r][kk + tig + 4];
                a[mf][3] = As[r + 8][kk + tig + 4];
            }
#pragma unroll
            for (int nf = 0; nf < 4; nf++) {
                int r = wn + nf * 8 + gid;
                b[nf][0] = Bs[r][kk + tig];
                b[nf][1] = Bs[r][kk + tig + 4];
            }
#pragma unroll
            for (int mf = 0; mf < 2; mf++)
#pragma unroll
                for (int nf = 0; nf < 4; nf++) mma8(acc[mf][nf], a[mf], b[nf]);
        }
        __syncthreads();
        if (it + 1 < nk) {
#pragma unroll
            for (int i = 0; i < 4; i++) {
                As[lr + 32 * i][lc + 0] = t32(pa[i].x);
                As[lr + 32 * i][lc + 1] = t32(pa[i].y);
                As[lr + 32 * i][lc + 2] = t32(pa[i].z);
                As[lr + 32 * i][lc + 3] = t32(pa[i].w);
            }
#pragma unroll
            for (int i = 0; i < 2; i++) {
                Bs[lr + 32 * i][lc + 0] = t32(pb[i].x);
                Bs[lr + 32 * i][lc + 1] = t32(pb[i].y);
                Bs[lr + 32 * i][lc + 2] = t32(pb[i].z);
                Bs[lr + 32 * i][lc + 3] = t32(pb[i].w);
            }
            __syncthreads();
        }
    }

    int nh = N >> 1;
#pragma unroll
    for (int mf = 0; mf < 2; mf++)
#pragma unroll
        for (int nf = 0; nf < 4; nf++) {
            int r0 = bm + wm + mf * 16 + gid;
            int c0 = bn + wn + nf * 8 + 2 * tig;
            if (r0 < M)
                H[(size_t)r0 * nh + (c0 >> 1)] =
                    __float22bfloat162_rn(make_float2(acc[mf][nf][0], acc[mf][nf][1]));
            if (r0 + 8 < M)
                H[(size_t)(r0 + 8) * nh + (c0 >> 1)] =
                    __float22bfloat162_rn(make_float2(acc[mf][nf][2], acc[mf][nf][3]));
        }
}

// ---------------- attention coefficients: s[n,h]=h·a_s, d[n,h]=h·a_d --------
template<int CT>
__global__ void k_sd(const float* __restrict__ as, const float* __restrict__ ad) {
    int w = (blockIdx.x * blockDim.x + threadIdx.x) >> 5;
    int lane = threadIdx.x & 31;
    if (w >= NN) return;
    float ps[4] = {0, 0, 0, 0}, pd[4] = {0, 0, 0, 0};
    if (CT == 512) {
        const float4* hp = (const float4*)g_h1b + (size_t)w * 64;
#pragma unroll
        for (int i = 0; i < 2; i++) {
            float4 hv = hp[lane + 32 * i];
            const __nv_bfloat162* hb = (const __nv_bfloat162*)&hv;
            int base = 256 * i + 8 * lane;
            float s8 = 0.f, d8 = 0.f;
#pragma unroll
            for (int k = 0; k < 4; k++) {
                float2 f = __bfloat1622float2(hb[k]);
                s8 += f.x * as[base + 2 * k] + f.y * as[base + 2 * k + 1];
                d8 += f.x * ad[base + 2 * k] + f.y * ad[base + 2 * k + 1];
            }
            int hd = 2 * i + (lane >> 4);
#pragma unroll
            for (int k = 0; k < 4; k++) {
                ps[k] += (hd == k) ? s8 : 0.f;
                pd[k] += (hd == k) ? d8 : 0.f;
            }
        }
    } else {
        uint2 hv = ((const uint2*)(g_h2b + (size_t)w * 64))[lane];
        float2 f0 = __bfloat1622float2(*(__nv_bfloat162*)&hv.x);
        float2 f1 = __bfloat1622float2(*(__nv_bfloat162*)&hv.y);
        int base = 4 * lane;
        float s4 = f0.x * as[base] + f0.y * as[base + 1] + f1.x * as[base + 2] + f1.y * as[base + 3];
        float d4 = f0.x * ad[base] + f0.y * ad[base + 1] + f1.x * ad[base + 2] + f1.y * ad[base + 3];
        int hd = lane >> 3;
#pragma unroll
        for (int k = 0; k < 4; k++) {
            ps[k] += (hd == k) ? s4 : 0.f;
            pd[k] += (hd == k) ? d4 : 0.f;
        }
    }
#pragma unroll
    for (int o = 16; o; o >>= 1) {
#pragma unroll
        for (int k = 0; k < 4; k++) {
            ps[k] += __shfl_xor_sync(0xffffffffu, ps[k], o);
            pd[k] += __shfl_xor_sync(0xffffffffu, pd[k], o);
        }
    }
    if (lane == 0) {
#pragma unroll
        for (int k = 0; k < 4; k++) { g_s[4 * w + k] = ps[k]; g_d[4 * w + k] = pd[k]; }
    }
}

// ---------------- warp-per-node segment softmax + aggregation ---------------
template<int CT>
__global__ void k_agg(const float* __restrict__ bias) {
    float* __restrict__ out = (CT == 512) ? g_o1 : g_o2;
    int w = (blockIdx.x * blockDim.x + threadIdx.x) >> 5;
    int lane = threadIdx.x & 31;
    if (w >= NN) return;
    int beg = g_rowptr[w], end = g_rowptr[w + 1];
    float4 dv = *(const float4*)(g_d + 4 * w);

    // pass 1: e = lrelu(s[src]+d[dst]); stage e; per-lane max
    float m0 = -1e30f, m1 = -1e30f, m2 = -1e30f, m3 = -1e30f;
    for (int j = beg + lane; j < end; j += 32) {
        int src = g_adj[j];
        float4 sv = *(const float4*)(g_s + 4 * src);
        float e0 = lrelu(sv.x + dv.x), e1 = lrelu(sv.y + dv.y);
        float e2 = lrelu(sv.z + dv.z), e3 = lrelu(sv.w + dv.w);
        *(float4*)(g_e + 4 * (size_t)j) = make_float4(e0, e1, e2, e3);
        m0 = fmaxf(m0, e0); m1 = fmaxf(m1, e1);
        m2 = fmaxf(m2, e2); m3 = fmaxf(m3, e3);
    }
#pragma unroll
    for (int o = 16; o; o >>= 1) {
        m0 = fmaxf(m0, __shfl_xor_sync(0xffffffffu, m0, o));
        m1 = fmaxf(m1, __shfl_xor_sync(0xffffffffu, m1, o));
        m2 = fmaxf(m2, __shfl_xor_sync(0xffffffffu, m2, o));
        m3 = fmaxf(m3, __shfl_xor_sync(0xffffffffu, m3, o));
    }
    __syncwarp();

    // pass 2: ex = exp(e-m); stage ex; den
    float d0 = 0, d1 = 0, d2 = 0, d3 = 0;
    for (int j = beg + lane; j < end; j += 32) {
        float4 ev = *(float4*)(g_e + 4 * (size_t)j);
        float x0 = expf(ev.x - m0), x1 = expf(ev.y - m1);
        float x2 = expf(ev.z - m2), x3 = expf(ev.w - m3);
        *(float4*)(g_e + 4 * (size_t)j) = make_float4(x0, x1, x2, x3);
        d0 += x0; d1 += x1; d2 += x2; d3 += x3;
    }
#pragma unroll
    for (int o = 16; o; o >>= 1) {
        d0 += __shfl_xor_sync(0xffffffffu, d0, o);
        d1 += __shfl_xor_sync(0xffffffffu, d1, o);
        d2 += __shfl_xor_sync(0xffffffffu, d2, o);
        d3 += __shfl_xor_sync(0xffffffffu, d3, o);
    }
    __syncwarp();

    // pass 3: acc = sum ex * h[src]  (bf16 gather, whole warp per edge)
    if (CT == 512) {
        float acc[2][8];
#pragma unroll
        for (int i = 0; i < 2; i++)
#pragma unroll
            for (int k = 0; k < 8; k++) acc[i][k] = 0.f;
        int hd0 = lane >> 4;
        for (int j = beg; j < end; j++) {
            int src = g_adj[j];                                // broadcast
            float4 xv = *(const float4*)(g_e + 4 * (size_t)j); // broadcast
            const float4* hp = (const float4*)g_h1b + (size_t)src * 64;
            float4 v0 = hp[lane];
            float4 v1 = hp[lane + 32];
            float w0 = sel4(xv.x, xv.y, xv.z, xv.w, hd0);
            float w1 = sel4(xv.x, xv.y, xv.z, xv.w, 2 + hd0);
            const __nv_bfloat162* b0 = (const __nv_bfloat162*)&v0;
            const __nv_bfloat162* b1 = (const __nv_bfloat162*)&v1;
#pragma unroll
            for (int k = 0; k < 4; k++) {
                float2 f0 = __bfloat1622float2(b0[k]);
                float2 f1 = __bfloat1622float2(b1[k]);
                acc[0][2 * k]     += w0 * f0.x;
                acc[0][2 * k + 1] += w0 * f0.y;
                acc[1][2 * k]     += w1 * f1.x;
                acc[1][2 * k + 1] += w1 * f1.y;
            }
        }
        float inv0 = 1.f / sel4(d0, d1, d2, d3, hd0);
        float inv1 = 1.f / sel4(d0, d1, d2, d3, 2 + hd0);
        float* op = out + (size_t)w * 512;
#pragma unroll
        for (int i = 0; i < 2; i++) {
            int base = 256 * i + 8 * lane;
            float inv = i ? inv1 : inv0;
            float4 bv0 = *(const float4*)(bias + base);
            float4 bv1 = *(const float4*)(bias + base + 4);
            float4 r0, r1;
            r0.x = eluf(acc[i][0] * inv + bv0.x);
            r0.y = eluf(acc[i][1] * inv + bv0.y);
            r0.z = eluf(acc[i][2] * inv + bv0.z);
            r0.w = eluf(acc[i][3] * inv + bv0.w);
            r1.x = eluf(acc[i][4] * inv + bv1.x);
            r1.y = eluf(acc[i][5] * inv + bv1.y);
            r1.z = eluf(acc[i][6] * inv + bv1.z);
            r1.w = eluf(acc[i][7] * inv + bv1.w);
            *(float4*)(op + base) = r0;
            *(float4*)(op + base + 4) = r1;
        }
    } else {
        float acc[4] = {0, 0, 0, 0};
        int hd = lane >> 3;
        for (int j = beg; j < end; j++) {
            int src = g_adj[j];
            float4 xv = *(const float4*)(g_e + 4 * (size_t)j);
            uint2 hv = ((const uint2*)(g_h2b + (size_t)src * 64))[lane];
            float wg = sel4(xv.x, xv.y, xv.z, xv.w, hd);
            float2 f0 = __bfloat1622float2(*(__nv_bfloat162*)&hv.x);
            float2 f1 = __bfloat1622float2(*(__nv_bfloat162*)&hv.y);
            acc[0] += wg * f0.x; acc[1] += wg * f0.y;
            acc[2] += wg * f1.x; acc[3] += wg * f1.y;
        }
        float inv = 1.f / sel4(d0, d1, d2, d3, hd);
        int base = 4 * lane;
        float4 bv = *(const float4*)(bias + base);
        float4 r;
        r.x = eluf(acc[0] * inv + bv.x);
        r.y = eluf(acc[1] * inv + bv.y);
        r.z = eluf(acc[2] * inv + bv.z);
        r.w = eluf(acc[3] * inv + bv.w);
        *(float4*)(out + (size_t)w * 128 + base) = r;
    }
}

// ---------------- layer3: h3 = o2 @ W3^T (8 outs) + s3/d3, warp per node ----
__global__ void k_l3(const float* __restrict__ W3, const float* __restrict__ a3s,
                     const float* __restrict__ a3d) {
    int w = (blockIdx.x * blockDim.x + threadIdx.x) >> 5;
    int lane = threadIdx.x & 31;
    if (w >= NN) return;
    float4 xv = ((const float4*)(g_o2 + (size_t)w * 128))[lane];
    float p[8];
#pragma unroll
    for (int o = 0; o < 8; o++) {
        float4 wv = ((const float4*)(W3 + o * 128))[lane];
        p[o] = xv.x * wv.x + xv.y * wv.y + xv.z * wv.z + xv.w * wv.w;
    }
#pragma unroll
    for (int off = 16; off; off >>= 1)
#pragma unroll
        for (int o = 0; o < 8; o++) p[o] += __shfl_xor_sync(0xffffffffu, p[o], off);
    if (lane == 0) {
        float ss = 0.f, dd = 0.f;
#pragma unroll
        for (int o = 0; o < 8; o++) {
            g_h3[w * 8 + o] = p[o];
            ss += p[o] * a3s[o];
            dd += p[o] * a3d[o];
        }
        g_s3[w] = ss; g_d3[w] = dd;
    }
}

// ---------------- layer3 aggregation: thread per node -----------------------
__global__ void k_agg3(const float* __restrict__ b3) {
    int n = blockIdx.x * blockDim.x + threadIdx.x;
    if (n >= NN) return;
    int beg = g_rowptr[n], end = g_rowptr[n + 1];
    float dv = g_d3[n];
    float m = -1e30f;
    for (int j = beg; j < end; j++) {
        float e = lrelu(g_s3[g_adj[j]] + dv);
        m = fmaxf(m, e);
    }
    float den = 0.f;
    float4 a0 = make_float4(0, 0, 0, 0), a1 = make_float4(0, 0, 0, 0);
    for (int j = beg; j < end; j++) {
        int src = g_adj[j];
        float ex = expf(lrelu(g_s3[src] + dv) - m);
        den += ex;
        float4 h0 = *(const float4*)(g_h3 + (size_t)src * 8);
        float4 h1 = *(const float4*)(g_h3 + (size_t)src * 8 + 4);
        a0.x += ex * h0.x; a0.y += ex * h0.y; a0.z += ex * h0.z; a0.w += ex * h0.w;
        a1.x += ex * h1.x; a1.y += ex * h1.y; a1.z += ex * h1.z; a1.w += ex * h1.w;
    }
    float inv = 1.f / den;
    float4 r0, r1;
    r0.x = eluf(a0.x * inv + b3[0]); r0.y = eluf(a0.y * inv + b3[1]);
    r0.z = eluf(a0.z * inv + b3[2]); r0.w = eluf(a0.w * inv + b3[3]);
    r1.x = eluf(a1.x * inv + b3[4]); r1.y = eluf(a1.y * inv + b3[5]);
    r1.z = eluf(a1.z * inv + b3[6]); r1.w = eluf(a1.w * inv + b3[7]);
    *(float4*)(g_o3 + (size_t)n * 8) = r0;
    *(float4*)(g_o3 + (size_t)n * 8 + 4) = r1;
}

// ---------------- edge MLP ----------------
__global__ void k_mlp(const int* __restrict__ ei, const float* __restrict__ ea,
                      const float* __restrict__ yr, const float* __restrict__ qt,
                      const float* __restrict__ f1w, const float* __restrict__ f1b,
                      const float* __restrict__ f2w, const float* __restrict__ f2b,
                      float* __restrict__ out) {
    __shared__ float w1s[16 * 19], b1s[16], w2s[16];
    __shared__ float b2s;
    int t = threadIdx.x;
    for (int i = t; i < 16 * 19; i += blockDim.x) w1s[i] = f1w[i];
    if (t < 16) { b1s[t] = f1b[t]; w2s[t] = f2w[t]; }
    if (t == 0) b2s = f2b[0];
    __syncthreads();
    int e = blockIdx.x * blockDim.x + t;
    if (e >= EE) return;
    int src = ei[e], dst = ei[EE + e];
    float4 s0 = *(const float4*)(g_o3 + (size_t)src * 8);
    float4 s1 = *(const float4*)(g_o3 + (size_t)src * 8 + 4);
    float4 q0 = *(const float4*)(g_o3 + (size_t)dst * 8);
    float4 q1 = *(const float4*)(g_o3 + (size_t)dst * 8 + 4);
    float z16 = ea[e], z17 = yr[e], z18 = qt[e];
    float res = b2s;
#pragma unroll
    for (int o = 0; o < 16; o++) {
        const float* wr = &w1s[o * 19];
        float a = b1s[o]
            + wr[0] * s0.x + wr[1] * s0.y + wr[2] * s0.z + wr[3] * s0.w
            + wr[4] * s1.x + wr[5] * s1.y + wr[6] * s1.z + wr[7] * s1.w
            + wr[8] * q0.x + wr[9] * q0.y + wr[10] * q0.z + wr[11] * q0.w
            + wr[12] * q1.x + wr[13] * q1.y + wr[14] * q1.z + wr[15] * q1.w
            + wr[16] * z16 + wr[17] * z17 + wr[18] * z18;
        res += w2s[o] * fmaxf(a, 0.f);
    }
    out[e] = res;
}

// ---------------- host ----------------
extern "C" void kernel_launch(void* const* d_in, const int* in_sizes, int n_in,
                              void* d_out, int out_size) {
    const float* x   = (const float*)d_in[0];
    const int*   ei  = (const int*)d_in[1];
    const float* ea  = (const float*)d_in[2];
    const float* yr  = (const float*)d_in[3];
    const float* qt  = (const float*)d_in[4];
    const float* W1  = (const float*)d_in[5];
    const float* a1s = (const float*)d_in[6];
    const float* a1d = (const float*)d_in[7];
    const float* b1  = (const float*)d_in[8];
    const float* W2  = (const float*)d_in[9];
    const float* a2s = (const float*)d_in[10];
    const float* a2d = (const float*)d_in[11];
    const float* b2  = (const float*)d_in[12];
    const float* W3  = (const float*)d_in[13];
    const float* a3s = (const float*)d_in[14];
    const float* a3d = (const float*)d_in[15];
    const float* b3  = (const float*)d_in[16];
    const float* f1w = (const float*)d_in[17];
    const float* f1b = (const float*)d_in[18];
    const float* f2w = (const float*)d_in[19];
    const float* f2b = (const float*)d_in[20];
    float* out = (float*)d_out;

    // CSR build (dst-sorted adjacency, self loop first per node)
    int nb = (NN + 255) / 256;   // 196
    k_initdeg<<<nb, 256>>>();
    k_count<<<(EE + 255) / 256, 256>>>(ei);
    k_scan1<<<nb, 256>>>();
    k_scan2<<<1, 256>>>();
    k_scan3<<<nb, 256>>>();
    k_scatter<<<(EE + 255) / 256, 256>>>(ei);

    int wblocks = (NN * 32 + 255) / 256;   // warp-per-node launches

    // layer 1: 128 -> 4x128 (tf32 tensor cores, bf16 out)
    dim3 g1(512 / 64, (NN + 127) / 128);
    gemm_tc<1><<<g1, 256>>>(x, W1, NN, 512, 128);
    k_sd<512><<<wblocks, 256>>>(a1s, a1d);
    k_agg<512><<<wblocks, 256>>>(b1);

    // layer 2: 512 -> 4x32 (tf32 tensor cores, bf16 out)
    dim3 g2(128 / 64, (NN + 127) / 128);
    gemm_tc<2><<<g2, 256>>>(nullptr, W2, NN, 128, 512);
    k_sd<128><<<wblocks, 256>>>(a2s, a2d);
    k_agg<128><<<wblocks, 256>>>(b2);

    // layer 3: 128 -> 1x8 (gemm + s/d fused), then aggregation
    k_l3<<<wblocks, 256>>>(W3, a3s, a3d);
    k_agg3<<<nb, 256>>>(b3);

    // edge MLP
    k_mlp<<<(EE + 255) / 256, 256>>>(ei, ea, yr, qt, f1w, f1b, f2w, f2b, out);
}